// round 13
// baseline (speedup 1.0000x reference)
#include <cuda_runtime.h>
#include <cuda_fp16.h>
#include <cstdint>

#define BATCH   16
#define CHX     256
#define NPOS    170
#define TT      64
#define NHEAD   8
#define HDIM    64
#define BN      (BATCH*NPOS)      // 2720
#define TOKENS  (BN*TT)           // 174080
#define NTSTR   (NPOS*TT)         // 10880
#define QE      (TOKENS*512)      // 89,128,960

// Device scratch (fp16). g_x/g_o2: [token][c 512].
__device__ __half g_x[QE];
__device__ __half g_w[4*512*512];   // [mat][n][k] row-major
__device__ __half g_o2[QE];

// ---------------------------------------------------------------------------
__device__ __forceinline__ void mma_f16(float* d, const uint32_t* a, const uint32_t* b) {
    asm volatile(
        "mma.sync.aligned.m16n8k16.row.col.f32.f16.f16.f32 "
        "{%0,%1,%2,%3},{%4,%5,%6,%7},{%8,%9},{%0,%1,%2,%3};\n"
        : "+f"(d[0]), "+f"(d[1]), "+f"(d[2]), "+f"(d[3])
        : "r"(a[0]), "r"(a[1]), "r"(a[2]), "r"(a[3]),
          "r"(b[0]), "r"(b[1]));
}

__device__ __forceinline__ void ldsm4(uint32_t* r, uint32_t addr) {
    asm volatile("ldmatrix.sync.aligned.m8n8.x4.shared.b16 {%0,%1,%2,%3}, [%4];"
                 : "=r"(r[0]), "=r"(r[1]), "=r"(r[2]), "=r"(r[3]) : "r"(addr));
}

__device__ __forceinline__ uint32_t packh2(float a, float b) {
    __half2 h = __floats2half2_rn(a, b);
    return *(uint32_t*)&h;
}

__device__ __forceinline__ void cpasync16(__half* smem_dst, const __half* gsrc) {
    uint32_t s = (uint32_t)__cvta_generic_to_shared(smem_dst);
    asm volatile("cp.async.cg.shared.global [%0], [%1], 16;\n"
                 :: "r"(s), "l"(gsrc) : "memory");
}
#define CP_COMMIT() asm volatile("cp.async.commit_group;\n" ::: "memory")
#define CP_WAIT2()  asm volatile("cp.async.wait_group 2;\n" ::: "memory")

// ---------------------------------------------------------------------------
// Prepass 1: x||tem -> g_x fp16 [token][c], via smem transpose.
// ---------------------------------------------------------------------------
__global__ void cvt_x_kernel(const float* __restrict__ x, const float* __restrict__ tem)
{
    __shared__ float smt[64 * 67];
    const int blk = blockIdx.x;
    const int b = blk / NPOS, n = blk % NPOS;
    const int tid = threadIdx.x;

    for (int chunk = 0; chunk < 8; chunk++) {
        const int c0 = chunk * 64;
        const float* src = (c0 < CHX)
            ? x   + (size_t)(b * CHX + c0) * NTSTR
            : tem + (size_t)(b * CHX + c0 - CHX) * NTSTR;
#pragma unroll
        for (int i = 0; i < 16; i++) {
            int idx = tid + i * 256;
            int cl = idx >> 6, t = idx & 63;
            smt[cl * 67 + t] = __ldg(&src[(size_t)cl * NTSTR + n * TT + t]);
        }
        __syncthreads();
#pragma unroll
        for (int i = 0; i < 16; i++) {
            int idx = tid + i * 256;
            int t = idx >> 6, cl = idx & 63;
            g_x[((size_t)(b * NPOS + n) * TT + t) * 512 + c0 + cl] =
                __float2half_rn(smt[cl * 67 + t]);
        }
        __syncthreads();
    }
}

// ---------------------------------------------------------------------------
// Prepass 2: weights -> g_w fp16 [mat][n][k]. 1M elems, grid 4096 x 256.
// ---------------------------------------------------------------------------
__global__ void cvt_w_kernel(const float* __restrict__ Wq, const float* __restrict__ Wk,
                             const float* __restrict__ Wv, const float* __restrict__ Wo)
{
    int e = blockIdx.x * 256 + threadIdx.x;
    int mat = e >> 18;
    int rem = e & 0x3FFFF;
    const float* W = (mat == 0) ? Wq : (mat == 1) ? Wk : (mat == 2) ? Wv : Wo;
    g_w[e] = __float2half_rn(__ldg(&W[rem]));
}

// ---------------------------------------------------------------------------
// GEMM core (unchanged from R11-win): Mtile 128 x Ntile 128 x Ktile 32,
// 4-slot depth-3 cp.async pipeline, 1 sync/iter, ldmatrix fragments.
// ---------------------------------------------------------------------------
#define STAGE_H 10240              // halfs per stage (A 128*40 + B 128*40)
#define PIPE_BYTES (4*STAGE_H*2)   // 81920

__device__ __forceinline__ void gemm_pipeline(const __half* aSrc, const __half* bSrc,
                                              __half* sm, float (&acc)[2][8][4],
                                              int tid, int mbase, int nbase)
{
    const int lane = tid & 31;
    const uint32_t smBase = (uint32_t)__cvta_generic_to_shared(sm);

    uint32_t aOff[2], bOff[4];
#pragma unroll
    for (int mi = 0; mi < 2; mi++)
        aOff[mi] = (uint32_t)((mbase + mi * 16 + (lane & 15)) * 80 + ((lane >> 4) & 1) * 16);
#pragma unroll
    for (int p = 0; p < 4; p++)
        bOff[p] = (uint32_t)(5120 * 2 +
                  (nbase + p * 16 + ((lane >> 4) & 1) * 8 + (lane & 7)) * 80 +
                  ((lane >> 3) & 1) * 16);

    auto issue = [&](int stage, int kt) {
        __half* As = sm + stage * STAGE_H;
        __half* Bs = As + 5120;
#pragma unroll
        for (int j = 0; j < 2; j++) {
            int cidx = tid + j * 256;
            int row = cidx >> 2, part = cidx & 3;
            cpasync16(As + row * 40 + part * 8, aSrc + (size_t)row * 512 + kt * 32 + part * 8);
            cpasync16(Bs + row * 40 + part * 8, bSrc + (size_t)row * 512 + kt * 32 + part * 8);
        }
    };

#pragma unroll
    for (int s = 0; s < 3; s++) { issue(s, s); CP_COMMIT(); }

    for (int it = 0; it < 16; it++) {
        CP_WAIT2();
        __syncthreads();
        int nx = it + 3;
        if (nx < 16) issue(nx & 3, nx);
        CP_COMMIT();

        const uint32_t stageB = smBase + (uint32_t)((it & 3) * STAGE_H * 2);
#pragma unroll
        for (int ks = 0; ks < 2; ks++) {
            uint32_t a[2][4];
            ldsm4(a[0], stageB + aOff[0] + ks * 32);
            ldsm4(a[1], stageB + aOff[1] + ks * 32);
            uint32_t b[4][4];
#pragma unroll
            for (int p = 0; p < 4; p++)
                ldsm4(b[p], stageB + bOff[p] + ks * 32);
#pragma unroll
            for (int p = 0; p < 4; p++) {
                mma_f16(acc[0][2 * p],     a[0], &b[p][0]);
                mma_f16(acc[1][2 * p],     a[1], &b[p][0]);
                mma_f16(acc[0][2 * p + 1], a[0], &b[p][2]);
                mma_f16(acc[1][2 * p + 1], a[1], &b[p][2]);
            }
        }
    }
}

// ---------------------------------------------------------------------------
// Fused QKV + attention. grid (4 cb, 1360 bn-pair), 256 threads, 1 CTA/SM.
// cb owns output channels cb*128..+127 of q/k/v = heads {2cb, 2cb+1}.
// smem: pipeline 80KB | Qs 34KB | Ks 34KB | Vt 34KB  (tiles stride 136 halfs)
// ---------------------------------------------------------------------------
#define QS_H   40960
#define KS_H   (QS_H + 17408)
#define VT_H   (KS_H + 17408)
#define FUSED_SMEM ((VT_H + 17408) * 2)   // 186368 B

__global__ __launch_bounds__(256, 1)
void fused_kernel(const float* __restrict__ bq, const float* __restrict__ bk,
                  const float* __restrict__ bv)
{
    extern __shared__ __half sm[];
    uint32_t* QsW = (uint32_t*)(sm + QS_H);
    uint32_t* KsW = (uint32_t*)(sm + KS_H);
    uint32_t* VtW = (uint32_t*)(sm + VT_H);

    const int tid = threadIdx.x;
    const int cb   = blockIdx.x;
    const int pair = blockIdx.y;

    const int lane = tid & 31, wid = tid >> 5;
    const int wm = wid & 3, wn = wid >> 2;
    const int g = lane >> 2, t4 = lane & 3;
    const int mbase = wm * 32, nbase = wn * 64;

    const __half* aSrc = g_x + (size_t)(pair * 128) * 512;

    // ---- three GEMMs: q, k, v for this channel block ----
    for (int mat = 0; mat < 3; mat++) {
        float acc[2][8][4];
#pragma unroll
        for (int mi = 0; mi < 2; mi++)
#pragma unroll
            for (int ni = 0; ni < 8; ni++)
#pragma unroll
                for (int j = 0; j < 4; j++) acc[mi][ni][j] = 0.f;

        const __half* bSrc = g_w + (size_t)(mat * 512 + cb * 128) * 512;
        gemm_pipeline(aSrc, bSrc, sm, acc, tid, mbase, nbase);
        __syncthreads();   // all compute done before epilogue/next-issue

        const float* bias = (mat == 0) ? bq : (mat == 1) ? bk : bv;
        uint32_t* EsW = (mat == 0) ? QsW : (mat == 1) ? KsW : (uint32_t*)sm;
#pragma unroll
        for (int mi = 0; mi < 2; mi++) {
            int rA = mbase + mi * 16 + g;
#pragma unroll
            for (int ni = 0; ni < 8; ni++) {
                int jj = nbase + ni * 8 + 2 * t4;
                int o = cb * 128 + jj;
                float b0 = __ldg(&bias[o]), b1 = __ldg(&bias[o + 1]);
                EsW[rA * 68 + (jj >> 1)]       = packh2(acc[mi][ni][0] + b0, acc[mi][ni][1] + b1);
                EsW[(rA + 8) * 68 + (jj >> 1)] = packh2(acc[mi][ni][2] + b0, acc[mi][ni][3] + b1);
            }
        }
    }
    __syncthreads();       // v staging complete

    // ---- transpose v staging (sm, [t][c] stride 136) -> Vt [c][t] ----
    {
        const __half* Es = sm;
        __half* Vt = sm + VT_H;
#pragma unroll
        for (int j = 0; j < 8; j++) {
            int idx = tid + j * 256;
            int ddg = idx & 127;            // local channel 0..127
            int tch = idx >> 7;             // 0..15, 8 tokens each
            int t0 = tch * 8;
            uint32_t w[4];
#pragma unroll
            for (int p = 0; p < 4; p++) {
                __half lo = Es[(t0 + 2 * p) * 136 + ddg];
                __half hi = Es[(t0 + 2 * p + 1) * 136 + ddg];
                w[p] = (uint32_t)__half_as_ushort(lo) | ((uint32_t)__half_as_ushort(hi) << 16);
            }
            *(uint4*)(sm + VT_H + ddg * 136 + t0) = *(uint4*)w;
        }
    }
    __syncthreads();       // Qs/Ks/Vt all ready

    // ---- attention: 4 instances (2 bn x 2 heads), 2 rounds x 2 warpgroups ----
    // Zero block barriers: each warp touches only its own 16 tile-rows of Qs;
    // Ks/Vt are read-only; rounds use disjoint row halves.
    const int hp = wid >> 2;        // head-in-block 0/1 (warpgroup)
    const int ws = wid & 3;         // warp slot within instance
    const int colw = hp * 32;       // word-column base of this head in Qs/Ks
    const int rbase = ws * 16;

    for (int r = 0; r < 2; r++) {
        const int qr = r * 64;                    // token-row base (bn within pair)
        const int rA_l = rbase + g, rB_l = rA_l + 8;
        const int rowA = qr + rA_l, rowB = qr + rB_l;

        float s[8][4];
#pragma unroll
        for (int ni = 0; ni < 8; ni++)
#pragma unroll
            for (int j = 0; j < 4; j++) s[ni][j] = 0.f;

#pragma unroll
        for (int ks = 0; ks < 4; ks++) {
            uint32_t a[4];
            a[0] = QsW[rowA * 68 + colw + 8 * ks + t4];
            a[1] = QsW[rowB * 68 + colw + 8 * ks + t4];
            a[2] = QsW[rowA * 68 + colw + 8 * ks + t4 + 4];
            a[3] = QsW[rowB * 68 + colw + 8 * ks + t4 + 4];
#pragma unroll
            for (int ni = 0; ni < 8; ni++) {
                uint32_t b[2];
                b[0] = KsW[(qr + ni * 8 + g) * 68 + colw + 8 * ks + t4];
                b[1] = KsW[(qr + ni * 8 + g) * 68 + colw + 8 * ks + t4 + 4];
                mma_f16(s[ni], a, b);
            }
        }

        // mask + softmax (f32, constants identical to reference)
        float mx0 = -1e30f, mx1 = -1e30f;
#pragma unroll
        for (int ni = 0; ni < 8; ni++) {
            int c0 = ni * 8 + 2 * t4, c1 = c0 + 1;
            s[ni][0] = (c0 <= rA_l) ? s[ni][0] * 0.125f : -32767.0f;
            s[ni][1] = (c1 <= rA_l) ? s[ni][1] * 0.125f : -32767.0f;
            s[ni][2] = (c0 <= rB_l) ? s[ni][2] * 0.125f : -32767.0f;
            s[ni][3] = (c1 <= rB_l) ? s[ni][3] * 0.125f : -32767.0f;
            mx0 = fmaxf(mx0, fmaxf(s[ni][0], s[ni][1]));
            mx1 = fmaxf(mx1, fmaxf(s[ni][2], s[ni][3]));
        }
        mx0 = fmaxf(mx0, __shfl_xor_sync(0xffffffffu, mx0, 1));
        mx0 = fmaxf(mx0, __shfl_xor_sync(0xffffffffu, mx0, 2));
        mx1 = fmaxf(mx1, __shfl_xor_sync(0xffffffffu, mx1, 1));
        mx1 = fmaxf(mx1, __shfl_xor_sync(0xffffffffu, mx1, 2));

        float sm0 = 0.f, sm1 = 0.f;
#pragma unroll
        for (int ni = 0; ni < 8; ni++) {
            s[ni][0] = __expf(s[ni][0] - mx0); sm0 += s[ni][0];
            s[ni][1] = __expf(s[ni][1] - mx0); sm0 += s[ni][1];
            s[ni][2] = __expf(s[ni][2] - mx1); sm1 += s[ni][2];
            s[ni][3] = __expf(s[ni][3] - mx1); sm1 += s[ni][3];
        }
        sm0 += __shfl_xor_sync(0xffffffffu, sm0, 1);
        sm0 += __shfl_xor_sync(0xffffffffu, sm0, 2);
        sm1 += __shfl_xor_sync(0xffffffffu, sm1, 1);
        sm1 += __shfl_xor_sync(0xffffffffu, sm1, 2);
        float inv0 = 1.f / sm0, inv1 = 1.f / sm1;

        // P (fp16) into own rows of Qs (overwrites q of this head, fully consumed)
#pragma unroll
        for (int ni = 0; ni < 8; ni++) {
            QsW[rowA * 68 + colw + ni * 4 + t4] = packh2(s[ni][0] * inv0, s[ni][1] * inv0);
            QsW[rowB * 68 + colw + ni * 4 + t4] = packh2(s[ni][2] * inv1, s[ni][3] * inv1);
        }
        __syncwarp();   // cross-lane P visibility within the warp

        float o[8][4];
#pragma unroll
        for (int ni = 0; ni < 8; ni++)
#pragma unroll
            for (int j = 0; j < 4; j++) o[ni][j] = 0.f;

#pragma unroll
        for (int ks = 0; ks < 4; ks++) {
            uint32_t a[4];
            a[0] = QsW[rowA * 68 + colw + 8 * ks + t4];
            a[1] = QsW[rowB * 68 + colw + 8 * ks + t4];
            a[2] = QsW[rowA * 68 + colw + 8 * ks + t4 + 4];
            a[3] = QsW[rowB * 68 + colw + 8 * ks + t4 + 4];
#pragma unroll
            for (int ni = 0; ni < 8; ni++) {
                uint32_t b[2];
                b[0] = VtW[(hp * 64 + ni * 8 + g) * 68 + r * 32 + 8 * ks + t4];
                b[1] = VtW[(hp * 64 + ni * 8 + g) * 68 + r * 32 + 8 * ks + t4 + 4];
                mma_f16(o[ni], a, b);
            }
        }
        __syncwarp();   // P reads done before O overwrites own rows

        // O (fp16) into own rows of Qs
#pragma unroll
        for (int ni = 0; ni < 8; ni++) {
            QsW[rowA * 68 + colw + ni * 4 + t4] = packh2(o[ni][0], o[ni][1]);
            QsW[rowB * 68 + colw + ni * 4 + t4] = packh2(o[ni][2], o[ni][3]);
        }
    }
    __syncthreads();

    // ---- dump O tile [128 rows][128 cols] -> g_o2[token][cb*128 ..] ----
#pragma unroll
    for (int j = 0; j < 8; j++) {
        int idx = tid + j * 256;
        int rr = idx >> 4, part = idx & 15;
        *(uint4*)(g_o2 + (size_t)(pair * 128 + rr) * 512 + cb * 128 + part * 8) =
            *(uint4*)&QsW[rr * 68 + part * 4];
    }
}

// ---------------------------------------------------------------------------
// Kernel 3: output projection + bias + ReLU. grid (4, 1360). Unchanged.
// ---------------------------------------------------------------------------
__global__ __launch_bounds__(256, 2)
void out_kernel(const float* __restrict__ bo, float* __restrict__ out)
{
    extern __shared__ __half sm[];
    __shared__ int outOff[128];

    const int tid = threadIdx.x;
    const int m0  = blockIdx.y * 128;
    const int r0  = blockIdx.x * 128;

    if (tid < 128) {
        int token = m0 + tid;
        int bn = token >> 6;
        int b = bn / NPOS, n = bn % NPOS;
        outOff[tid] = (b * 512 * NPOS + n) * TT + (token & 63);
    }

    const int lane = tid & 31, wid = tid >> 5;
    const int wm = wid & 3, wn = wid >> 2;
    const int g = lane >> 2, t4 = lane & 3;
    const int mbase = wm * 32, nbase = wn * 64;

    float acc[2][8][4];
#pragma unroll
    for (int mi = 0; mi < 2; mi++)
#pragma unroll
        for (int ni = 0; ni < 8; ni++)
#pragma unroll
            for (int j = 0; j < 4; j++) acc[mi][ni][j] = 0.f;

    const __half* aSrc = g_o2 + (size_t)m0 * 512;
    const __half* bSrc = g_w + (size_t)(3 * 512 + r0) * 512;

    gemm_pipeline(aSrc, bSrc, sm, acc, tid, mbase, nbase);
    __syncthreads();

    // epilogue: bias + relu + scatter to [B,512,N,T] (t-contiguous 32B runs)
#pragma unroll
    for (int mi = 0; mi < 2; mi++) {
        int rloc = mbase + mi * 16 + g;
        int off0 = outOff[rloc];
        int off1 = outOff[rloc + 8];
#pragma unroll
        for (int ni = 0; ni < 8; ni++) {
            int jj = nbase + ni * 8 + 2 * t4;
            int o = r0 + jj;
            float b0 = __ldg(&bo[o]), b1 = __ldg(&bo[o + 1]);
            out[off0 + o * NTSTR]       = fmaxf(acc[mi][ni][0] + b0, 0.f);
            out[off0 + (o + 1) * NTSTR] = fmaxf(acc[mi][ni][1] + b1, 0.f);
            out[off1 + o * NTSTR]       = fmaxf(acc[mi][ni][2] + b0, 0.f);
            out[off1 + (o + 1) * NTSTR] = fmaxf(acc[mi][ni][3] + b1, 0.f);
        }
    }
}

// ---------------------------------------------------------------------------
extern "C" void kernel_launch(void* const* d_in, const int* in_sizes, int n_in,
                              void* d_out, int out_size)
{
    const float* x   = (const float*)d_in[0];
    const float* tem = (const float*)d_in[1];
    const float* Wq  = (const float*)d_in[2];
    const float* bq  = (const float*)d_in[3];
    const float* Wk  = (const float*)d_in[4];
    const float* bk  = (const float*)d_in[5];
    const float* Wv  = (const float*)d_in[6];
    const float* bv  = (const float*)d_in[7];
    const float* Wo  = (const float*)d_in[8];
    const float* bo  = (const float*)d_in[9];
    float* out = (float*)d_out;

    cudaFuncSetAttribute(fused_kernel, cudaFuncAttributeMaxDynamicSharedMemorySize, FUSED_SMEM);
    cudaFuncSetAttribute(out_kernel, cudaFuncAttributeMaxDynamicSharedMemorySize, PIPE_BYTES);

    cvt_x_kernel<<<BN, 256>>>(x, tem);
    cvt_w_kernel<<<4096, 256>>>(Wq, Wk, Wv, Wo);

    dim3 g1(4, BN / 2);
    fused_kernel<<<g1, 256, FUSED_SMEM>>>(bq, bk, bv);

    dim3 g3(4, BN / 2);
    out_kernel<<<g3, 256, PIPE_BYTES>>>(bo, out);
}

// round 14
// speedup vs baseline: 1.0900x; 1.0900x over previous
#include <cuda_runtime.h>
#include <cuda_fp16.h>
#include <cstdint>

#define BATCH   16
#define CHX     256
#define NPOS    170
#define TT      64
#define NHEAD   8
#define HDIM    64
#define BN      (BATCH*NPOS)      // 2720
#define TOKENS  (BN*TT)           // 174080
#define NTSTR   (NPOS*TT)         // 10880
#define QE      (TOKENS*512)      // 89,128,960

// Device scratch (fp16). g_x/g_o2: [token][c 512]. g_q/g_k: per-(bn,h) [t][dd].
// g_v: per-(bn,h) [dd][t] (pre-transposed).
__device__ __half g_x[QE];
__device__ __half g_w[4*512*512];   // [mat][n][k] row-major
__device__ __half g_q[QE];
__device__ __half g_k[QE];
__device__ __half g_v[QE];
__device__ __half g_o2[QE];

// ---------------------------------------------------------------------------
__device__ __forceinline__ void mma_f16(float* d, const uint32_t* a, const uint32_t* b) {
    asm volatile(
        "mma.sync.aligned.m16n8k16.row.col.f32.f16.f16.f32 "
        "{%0,%1,%2,%3},{%4,%5,%6,%7},{%8,%9},{%0,%1,%2,%3};\n"
        : "+f"(d[0]), "+f"(d[1]), "+f"(d[2]), "+f"(d[3])
        : "r"(a[0]), "r"(a[1]), "r"(a[2]), "r"(a[3]),
          "r"(b[0]), "r"(b[1]));
}

__device__ __forceinline__ void ldsm4(uint32_t* r, uint32_t addr) {
    asm volatile("ldmatrix.sync.aligned.m8n8.x4.shared.b16 {%0,%1,%2,%3}, [%4];"
                 : "=r"(r[0]), "=r"(r[1]), "=r"(r[2]), "=r"(r[3]) : "r"(addr));
}

__device__ __forceinline__ uint32_t packh2(float a, float b) {
    __half2 h = __floats2half2_rn(a, b);
    return *(uint32_t*)&h;
}

__device__ __forceinline__ void cpasync16(__half* smem_dst, const __half* gsrc) {
    uint32_t s = (uint32_t)__cvta_generic_to_shared(smem_dst);
    asm volatile("cp.async.cg.shared.global [%0], [%1], 16;\n"
                 :: "r"(s), "l"(gsrc) : "memory");
}
#define CP_COMMIT() asm volatile("cp.async.commit_group;\n" ::: "memory")
#define CP_WAIT2()  asm volatile("cp.async.wait_group 2;\n" ::: "memory")

// ---------------------------------------------------------------------------
// Prepass 1: x||tem -> g_x fp16 [token][c], via smem transpose.
// ---------------------------------------------------------------------------
__global__ void cvt_x_kernel(const float* __restrict__ x, const float* __restrict__ tem)
{
    __shared__ float smt[64 * 67];
    const int blk = blockIdx.x;
    const int b = blk / NPOS, n = blk % NPOS;
    const int tid = threadIdx.x;

    for (int chunk = 0; chunk < 8; chunk++) {
        const int c0 = chunk * 64;
        const float* src = (c0 < CHX)
            ? x   + (size_t)(b * CHX + c0) * NTSTR
            : tem + (size_t)(b * CHX + c0 - CHX) * NTSTR;
#pragma unroll
        for (int i = 0; i < 16; i++) {
            int idx = tid + i * 256;
            int cl = idx >> 6, t = idx & 63;
            smt[cl * 67 + t] = __ldg(&src[(size_t)cl * NTSTR + n * TT + t]);
        }
        __syncthreads();
#pragma unroll
        for (int i = 0; i < 16; i++) {
            int idx = tid + i * 256;
            int t = idx >> 6, cl = idx & 63;
            g_x[((size_t)(b * NPOS + n) * TT + t) * 512 + c0 + cl] =
                __float2half_rn(smt[cl * 67 + t]);
        }
        __syncthreads();
    }
}

// ---------------------------------------------------------------------------
// Prepass 2: weights -> g_w fp16 [mat][n][k]. 1M elems, grid 4096 x 256.
// ---------------------------------------------------------------------------
__global__ void cvt_w_kernel(const float* __restrict__ Wq, const float* __restrict__ Wk,
                             const float* __restrict__ Wv, const float* __restrict__ Wo)
{
    int e = blockIdx.x * 256 + threadIdx.x;
    int mat = e >> 18;
    int rem = e & 0x3FFFF;
    const float* W = (mat == 0) ? Wq : (mat == 1) ? Wk : (mat == 2) ? Wv : Wo;
    g_w[e] = __float2half_rn(__ldg(&W[rem]));
}

// ---------------------------------------------------------------------------
// GEMM core: Mtile 128 x Ntile 64 x Ktile 32, fp16, f32 accum.
// Stage: A 128*40 + B 64*40 halfs = 15360 B; 4 stages = 60 KB -> 3 CTAs/SM.
// 4-slot depth-3 cp.async pipeline, 1 sync/iter, ldmatrix fragments.
// 8 warps: wm = wid&3 (32 rows), wn = wid>>2 (32 cols). acc[2][4][4].
// ---------------------------------------------------------------------------
#define STAGE_H 7680               // halfs per stage
#define PIPE_BYTES (4*STAGE_H*2)   // 61440

__device__ __forceinline__ void gemm_pipeline(const __half* aSrc, const __half* bSrc,
                                              __half* sm, float (&acc)[2][4][4],
                                              int tid, int mbase, int nbase)
{
    const int lane = tid & 31;
    const uint32_t smBase = (uint32_t)__cvta_generic_to_shared(sm);

    uint32_t aOff[2], bOff[2];
#pragma unroll
    for (int mi = 0; mi < 2; mi++)
        aOff[mi] = (uint32_t)((mbase + mi * 16 + (lane & 15)) * 80 + ((lane >> 4) & 1) * 16);
#pragma unroll
    for (int p = 0; p < 2; p++)
        bOff[p] = (uint32_t)(5120 * 2 +
                  (nbase + p * 16 + ((lane >> 4) & 1) * 8 + (lane & 7)) * 80 +
                  ((lane >> 3) & 1) * 16);

    auto issue = [&](int stage, int kt) {
        __half* As = sm + stage * STAGE_H;
        __half* Bs = As + 5120;
#pragma unroll
        for (int j = 0; j < 2; j++) {       // A: 128 rows x 4 parts
            int cidx = tid + j * 256;
            int row = cidx >> 2, part = cidx & 3;
            cpasync16(As + row * 40 + part * 8, aSrc + (size_t)row * 512 + kt * 32 + part * 8);
        }
        {                                   // B: 64 rows x 4 parts
            int row = tid >> 2, part = tid & 3;
            cpasync16(Bs + row * 40 + part * 8, bSrc + (size_t)row * 512 + kt * 32 + part * 8);
        }
    };

#pragma unroll
    for (int s = 0; s < 3; s++) { issue(s, s); CP_COMMIT(); }

    for (int it = 0; it < 16; it++) {
        CP_WAIT2();
        __syncthreads();
        int nx = it + 3;
        if (nx < 16) issue(nx & 3, nx);
        CP_COMMIT();

        const uint32_t stageB = smBase + (uint32_t)((it & 3) * STAGE_H * 2);
#pragma unroll
        for (int ks = 0; ks < 2; ks++) {
            uint32_t a[2][4];
            ldsm4(a[0], stageB + aOff[0] + ks * 32);
            ldsm4(a[1], stageB + aOff[1] + ks * 32);
            uint32_t b[2][4];
            ldsm4(b[0], stageB + bOff[0] + ks * 32);
            ldsm4(b[1], stageB + bOff[1] + ks * 32);
#pragma unroll
            for (int p = 0; p < 2; p++) {
                mma_f16(acc[0][2 * p],     a[0], &b[p][0]);
                mma_f16(acc[1][2 * p],     a[1], &b[p][0]);
                mma_f16(acc[0][2 * p + 1], a[0], &b[p][2]);
                mma_f16(acc[1][2 * p + 1], a[1], &b[p][2]);
            }
        }
    }
}

// ---------------------------------------------------------------------------
// Kernel 1: QKV projection. grid (24, 1360): x = mat*8 + head (64-ch block).
// Epilogue stages to smem (stride 36 words, 16B-aligned rows) then coalesced
// 16B stores; v written pre-transposed [dd][t].
// ---------------------------------------------------------------------------
__global__ __launch_bounds__(256, 3)
void qkv_kernel(const float* __restrict__ bq, const float* __restrict__ bk,
                const float* __restrict__ bv)
{
    extern __shared__ __half sm[];

    const int tid = threadIdx.x;
    const int bn0 = blockIdx.y * 2;
    const int vx  = blockIdx.x;
    const int mat = vx >> 3;            // 0:q 1:k 2:v
    const int nb  = vx & 7;             // head index (64-ch block)
    const int r0  = nb * 64;
    const float* bias = (mat == 0) ? bq : (mat == 1) ? bk : bv;

    const int lane = tid & 31, wid = tid >> 5;
    const int wm = wid & 3, wn = wid >> 2;
    const int g = lane >> 2, t4 = lane & 3;
    const int mbase = wm * 32, nbase = wn * 32;

    float acc[2][4][4];
#pragma unroll
    for (int mi = 0; mi < 2; mi++)
#pragma unroll
        for (int ni = 0; ni < 4; ni++)
#pragma unroll
            for (int j = 0; j < 4; j++) acc[mi][ni][j] = 0.f;

    const __half* aSrc = g_x + (size_t)(bn0 * TT) * 512;
    const __half* bSrc = g_w + (size_t)(mat * 512 + r0) * 512;

    gemm_pipeline(aSrc, bSrc, sm, acc, tid, mbase, nbase);
    __syncthreads();

    // ---- stage 128 rows x 64 ch to smem (stride 36 words = 144 B) ----
    uint32_t* EsW = (uint32_t*)sm;
#pragma unroll
    for (int mi = 0; mi < 2; mi++) {
        int rA = mbase + mi * 16 + g;
#pragma unroll
        for (int ni = 0; ni < 4; ni++) {
            int jj = nbase + ni * 8 + 2 * t4;
            int o = r0 + jj;
            float b0 = __ldg(&bias[o]), b1 = __ldg(&bias[o + 1]);
            EsW[rA * 36 + (jj >> 1)]       = packh2(acc[mi][ni][0] + b0, acc[mi][ni][1] + b1);
            EsW[(rA + 8) * 36 + (jj >> 1)] = packh2(acc[mi][ni][2] + b0, acc[mi][ni][3] + b1);
        }
    }
    __syncthreads();

    if (mat < 2) {
        __half* dst = (mat == 0) ? g_q : g_k;
#pragma unroll
        for (int j = 0; j < 4; j++) {
            int idx = tid + j * 256;            // 128 rows x 8 parts
            int trow = idx >> 3, part = idx & 7;
            int bn = bn0 + (trow >> 6), t = trow & 63;
            *(uint4*)(dst + (size_t)(bn * NHEAD + nb) * 4096 + t * 64 + part * 8) =
                *(uint4*)&EsW[trow * 36 + part * 4];
        }
    } else {
        // v transposed: g_v[(bn,h)][dd][t]; staging stride 72 halfs
        const __half* Es = sm;
#pragma unroll
        for (int j = 0; j < 4; j++) {
            int idx = tid + j * 256;            // 64 ch x 16 token-chunks
            int ddg = idx & 63;
            int tch = idx >> 6;                 // 0..15
            int bnh = tch >> 3, t0 = (tch & 7) * 8;
            uint32_t w[4];
#pragma unroll
            for (int p = 0; p < 4; p++) {
                __half lo = Es[(bnh * 64 + t0 + 2 * p) * 72 + ddg];
                __half hi = Es[(bnh * 64 + t0 + 2 * p + 1) * 72 + ddg];
                w[p] = (uint32_t)__half_as_ushort(lo) | ((uint32_t)__half_as_ushort(hi) << 16);
            }
            int bn = bn0 + bnh;
            *(uint4*)(g_v + (size_t)(bn * NHEAD + nb) * 4096 + ddg * 64 + t0) = *(uint4*)w;
        }
    }
}

// ---------------------------------------------------------------------------
// Kernel 2: causal attention per (bn, head). Unchanged (DRAM-bound at 68%).
// ---------------------------------------------------------------------------
#define SATT 36

__global__ __launch_bounds__(128)
void attn_kernel()
{
    __shared__ __half Qs[64 * 72];   // Q -> P -> O
    __shared__ __half Ks[64 * 72];   // K -> V^T
    uint32_t* QsW = (uint32_t*)Qs;
    uint32_t* KsW = (uint32_t*)Ks;

    const int tid = threadIdx.x;
    const int lane = tid & 31, wid = tid >> 5;
    const int g = lane >> 2, t4 = lane & 3;
    const int bh = blockIdx.x;
    const size_t base = (size_t)bh * 4096;

#pragma unroll
    for (int j = 0; j < 4; j++) {
        int idx = tid + j * 128;
        int t = idx >> 3, part = idx & 7;
        *(uint4*)&QsW[t * SATT + part * 4] = *(const uint4*)(g_q + base + t * 64 + part * 8);
        *(uint4*)&KsW[t * SATT + part * 4] = *(const uint4*)(g_k + base + t * 64 + part * 8);
    }
    __syncthreads();

    const int rbase = wid * 16;
    const int rA = rbase + g, rB = rA + 8;

    float s[8][4];
#pragma unroll
    for (int ni = 0; ni < 8; ni++)
#pragma unroll
        for (int j = 0; j < 4; j++) s[ni][j] = 0.f;

#pragma unroll
    for (int ks = 0; ks < 4; ks++) {
        uint32_t a[4];
        a[0] = QsW[rA * SATT + 8 * ks + t4];
        a[1] = QsW[rB * SATT + 8 * ks + t4];
        a[2] = QsW[rA * SATT + 8 * ks + t4 + 4];
        a[3] = QsW[rB * SATT + 8 * ks + t4 + 4];
#pragma unroll
        for (int ni = 0; ni < 8; ni++) {
            uint32_t b[2];
            b[0] = KsW[(ni * 8 + g) * SATT + 8 * ks + t4];
            b[1] = KsW[(ni * 8 + g) * SATT + 8 * ks + t4 + 4];
            mma_f16(s[ni], a, b);
        }
    }

    float mx0 = -1e30f, mx1 = -1e30f;
#pragma unroll
    for (int ni = 0; ni < 8; ni++) {
        int c0 = ni * 8 + 2 * t4, c1 = c0 + 1;
        s[ni][0] = (c0 <= rA) ? s[ni][0] * 0.125f : -32767.0f;
        s[ni][1] = (c1 <= rA) ? s[ni][1] * 0.125f : -32767.0f;
        s[ni][2] = (c0 <= rB) ? s[ni][2] * 0.125f : -32767.0f;
        s[ni][3] = (c1 <= rB) ? s[ni][3] * 0.125f : -32767.0f;
        mx0 = fmaxf(mx0, fmaxf(s[ni][0], s[ni][1]));
        mx1 = fmaxf(mx1, fmaxf(s[ni][2], s[ni][3]));
    }
    mx0 = fmaxf(mx0, __shfl_xor_sync(0xffffffffu, mx0, 1));
    mx0 = fmaxf(mx0, __shfl_xor_sync(0xffffffffu, mx0, 2));
    mx1 = fmaxf(mx1, __shfl_xor_sync(0xffffffffu, mx1, 1));
    mx1 = fmaxf(mx1, __shfl_xor_sync(0xffffffffu, mx1, 2));

    float sm0 = 0.f, sm1 = 0.f;
#pragma unroll
    for (int ni = 0; ni < 8; ni++) {
        s[ni][0] = __expf(s[ni][0] - mx0); sm0 += s[ni][0];
        s[ni][1] = __expf(s[ni][1] - mx0); sm0 += s[ni][1];
        s[ni][2] = __expf(s[ni][2] - mx1); sm1 += s[ni][2];
        s[ni][3] = __expf(s[ni][3] - mx1); sm1 += s[ni][3];
    }
    sm0 += __shfl_xor_sync(0xffffffffu, sm0, 1);
    sm0 += __shfl_xor_sync(0xffffffffu, sm0, 2);
    sm1 += __shfl_xor_sync(0xffffffffu, sm1, 1);
    sm1 += __shfl_xor_sync(0xffffffffu, sm1, 2);
    float inv0 = 1.f / sm0, inv1 = 1.f / sm1;

#pragma unroll
    for (int ni = 0; ni < 8; ni++) {
        QsW[rA * SATT + ni * 4 + t4] = packh2(s[ni][0] * inv0, s[ni][1] * inv0);
        QsW[rB * SATT + ni * 4 + t4] = packh2(s[ni][2] * inv1, s[ni][3] * inv1);
    }

    __syncthreads();
#pragma unroll
    for (int j = 0; j < 4; j++) {
        int idx = tid + j * 128;
        int dd = idx >> 3, part = idx & 7;
        *(uint4*)&KsW[dd * SATT + part * 4] = *(const uint4*)(g_v + base + dd * 64 + part * 8);
    }
    __syncthreads();

    float o[8][4];
#pragma unroll
    for (int ni = 0; ni < 8; ni++)
#pragma unroll
        for (int j = 0; j < 4; j++) o[ni][j] = 0.f;

#pragma unroll
    for (int ks = 0; ks < 4; ks++) {
        uint32_t a[4];
        a[0] = QsW[rA * SATT + 8 * ks + t4];
        a[1] = QsW[rB * SATT + 8 * ks + t4];
        a[2] = QsW[rA * SATT + 8 * ks + t4 + 4];
        a[3] = QsW[rB * SATT + 8 * ks + t4 + 4];
#pragma unroll
        for (int ni = 0; ni < 8; ni++) {
            uint32_t b[2];
            b[0] = KsW[(ni * 8 + g) * SATT + 8 * ks + t4];
            b[1] = KsW[(ni * 8 + g) * SATT + 8 * ks + t4 + 4];
            mma_f16(o[ni], a, b);
        }
    }
    __syncthreads();

#pragma unroll
    for (int ni = 0; ni < 8; ni++) {
        QsW[rA * SATT + ni * 4 + t4] = packh2(o[ni][0], o[ni][1]);
        QsW[rB * SATT + ni * 4 + t4] = packh2(o[ni][2], o[ni][3]);
    }
    __syncthreads();

    const int bn = bh >> 3, h = bh & 7;
#pragma unroll
    for (int j = 0; j < 4; j++) {
        int idx = tid + j * 128;
        int t = idx >> 3, part = idx & 7;
        uint4 v = *(uint4*)&QsW[t * SATT + part * 4];
        *(uint4*)(g_o2 + ((size_t)bn * 64 + t) * 512 + h * 64 + part * 8) = v;
    }
}

// ---------------------------------------------------------------------------
// Kernel 3: output projection + bias + ReLU. grid (8, 1360).
// ---------------------------------------------------------------------------
__global__ __launch_bounds__(256, 3)
void out_kernel(const float* __restrict__ bo, float* __restrict__ out)
{
    extern __shared__ __half sm[];
    __shared__ int outOff[128];

    const int tid = threadIdx.x;
    const int m0  = blockIdx.y * 128;
    const int r0  = blockIdx.x * 64;

    if (tid < 128) {
        int token = m0 + tid;
        int bn = token >> 6;
        int b = bn / NPOS, n = bn % NPOS;
        outOff[tid] = (b * 512 * NPOS + n) * TT + (token & 63);
    }

    const int lane = tid & 31, wid = tid >> 5;
    const int wm = wid & 3, wn = wid >> 2;
    const int g = lane >> 2, t4 = lane & 3;
    const int mbase = wm * 32, nbase = wn * 32;

    float acc[2][4][4];
#pragma unroll
    for (int mi = 0; mi < 2; mi++)
#pragma unroll
        for (int ni = 0; ni < 4; ni++)
#pragma unroll
            for (int j = 0; j < 4; j++) acc[mi][ni][j] = 0.f;

    const __half* aSrc = g_o2 + (size_t)m0 * 512;
    const __half* bSrc = g_w + (size_t)(3 * 512 + r0) * 512;

    gemm_pipeline(aSrc, bSrc, sm, acc, tid, mbase, nbase);
    __syncthreads();

    // epilogue: bias + relu + scatter to [B,512,N,T] (t-contiguous runs)
#pragma unroll
    for (int mi = 0; mi < 2; mi++) {
        int rloc = mbase + mi * 16 + g;
        int off0 = outOff[rloc];
        int off1 = outOff[rloc + 8];
#pragma unroll
        for (int ni = 0; ni < 4; ni++) {
            int jj = nbase + ni * 8 + 2 * t4;
            int o = r0 + jj;
            float b0 = __ldg(&bo[o]), b1 = __ldg(&bo[o + 1]);
            out[off0 + o * NTSTR]       = fmaxf(acc[mi][ni][0] + b0, 0.f);
            out[off0 + (o + 1) * NTSTR] = fmaxf(acc[mi][ni][1] + b1, 0.f);
            out[off1 + o * NTSTR]       = fmaxf(acc[mi][ni][2] + b0, 0.f);
            out[off1 + (o + 1) * NTSTR] = fmaxf(acc[mi][ni][3] + b1, 0.f);
        }
    }
}

// ---------------------------------------------------------------------------
extern "C" void kernel_launch(void* const* d_in, const int* in_sizes, int n_in,
                              void* d_out, int out_size)
{
    const float* x   = (const float*)d_in[0];
    const float* tem = (const float*)d_in[1];
    const float* Wq  = (const float*)d_in[2];
    const float* bq  = (const float*)d_in[3];
    const float* Wk  = (const float*)d_in[4];
    const float* bk  = (const float*)d_in[5];
    const float* Wv  = (const float*)d_in[6];
    const float* bv  = (const float*)d_in[7];
    const float* Wo  = (const float*)d_in[8];
    const float* bo  = (const float*)d_in[9];
    float* out = (float*)d_out;

    cudaFuncSetAttribute(qkv_kernel, cudaFuncAttributeMaxDynamicSharedMemorySize, PIPE_BYTES);
    cudaFuncSetAttribute(out_kernel, cudaFuncAttributeMaxDynamicSharedMemorySize, PIPE_BYTES);

    cvt_x_kernel<<<BN, 256>>>(x, tem);
    cvt_w_kernel<<<4096, 256>>>(Wq, Wk, Wv, Wo);

    dim3 g1(24, BN / 2);
    qkv_kernel<<<g1, 256, PIPE_BYTES>>>(bq, bk, bv);

    attn_kernel<<<BN * NHEAD, 128>>>();

    dim3 g3(8, BN / 2);
    out_kernel<<<g3, 256, PIPE_BYTES>>>(bo, out);
}

// round 16
// speedup vs baseline: 1.5142x; 1.3892x over previous
#include <cuda_runtime.h>
#include <cuda_fp16.h>
#include <cstdint>

#define BATCH   16
#define CHX     256
#define NPOS    170
#define TT      64
#define NHEAD   8
#define HDIM    64
#define BN      (BATCH*NPOS)      // 2720
#define TOKENS  (BN*TT)           // 174080
#define NTSTR   (NPOS*TT)         // 10880
#define QE      (TOKENS*512)      // 89,128,960

// Device scratch (fp16). g_x/g_o2: [token][c 512]. g_q/g_k: per-(bn,h) [t][dd].
// g_v: per-(bn,h) [dd][t] (pre-transposed).
__device__ __half g_x[QE];
__device__ __half g_w[4*512*512];   // [mat][n][k] row-major
__device__ __half g_q[QE];
__device__ __half g_k[QE];
__device__ __half g_v[QE];
__device__ __half g_o2[QE];

// ---------------------------------------------------------------------------
__device__ __forceinline__ void mma_f16(float* d, const uint32_t* a, const uint32_t* b) {
    asm volatile(
        "mma.sync.aligned.m16n8k16.row.col.f32.f16.f16.f32 "
        "{%0,%1,%2,%3},{%4,%5,%6,%7},{%8,%9},{%0,%1,%2,%3};\n"
        : "+f"(d[0]), "+f"(d[1]), "+f"(d[2]), "+f"(d[3])
        : "r"(a[0]), "r"(a[1]), "r"(a[2]), "r"(a[3]),
          "r"(b[0]), "r"(b[1]));
}

__device__ __forceinline__ void ldsm4(uint32_t* r, uint32_t addr) {
    asm volatile("ldmatrix.sync.aligned.m8n8.x4.shared.b16 {%0,%1,%2,%3}, [%4];"
                 : "=r"(r[0]), "=r"(r[1]), "=r"(r[2]), "=r"(r[3]) : "r"(addr));
}

__device__ __forceinline__ uint32_t packh2(float a, float b) {
    __half2 h = __floats2half2_rn(a, b);
    return *(uint32_t*)&h;
}

__device__ __forceinline__ void cpasync16(__half* smem_dst, const __half* gsrc) {
    uint32_t s = (uint32_t)__cvta_generic_to_shared(smem_dst);
    asm volatile("cp.async.cg.shared.global [%0], [%1], 16;\n"
                 :: "r"(s), "l"(gsrc) : "memory");
}
#define CP_COMMIT() asm volatile("cp.async.commit_group;\n" ::: "memory")
#define CP_WAIT1()  asm volatile("cp.async.wait_group 1;\n" ::: "memory")
#define CP_WAIT0()  asm volatile("cp.async.wait_group 0;\n" ::: "memory")

// ---------------------------------------------------------------------------
// Prepass 1: x||tem -> g_x fp16 [token][c], via smem transpose.
// ---------------------------------------------------------------------------
__global__ void cvt_x_kernel(const float* __restrict__ x, const float* __restrict__ tem)
{
    __shared__ float smt[64 * 67];
    const int blk = blockIdx.x;
    const int b = blk / NPOS, n = blk % NPOS;
    const int tid = threadIdx.x;

    for (int chunk = 0; chunk < 8; chunk++) {
        const int c0 = chunk * 64;
        const float* src = (c0 < CHX)
            ? x   + (size_t)(b * CHX + c0) * NTSTR
            : tem + (size_t)(b * CHX + c0 - CHX) * NTSTR;
#pragma unroll
        for (int i = 0; i < 16; i++) {
            int idx = tid + i * 256;
            int cl = idx >> 6, t = idx & 63;
            smt[cl * 67 + t] = __ldg(&src[(size_t)cl * NTSTR + n * TT + t]);
        }
        __syncthreads();
#pragma unroll
        for (int i = 0; i < 16; i++) {
            int idx = tid + i * 256;
            int t = idx >> 6, cl = idx & 63;
            g_x[((size_t)(b * NPOS + n) * TT + t) * 512 + c0 + cl] =
                __float2half_rn(smt[cl * 67 + t]);
        }
        __syncthreads();
    }
}

// ---------------------------------------------------------------------------
// Prepass 2: weights -> g_w fp16 [mat][n][k].
// ---------------------------------------------------------------------------
__global__ void cvt_w_kernel(const float* __restrict__ Wq, const float* __restrict__ Wk,
                             const float* __restrict__ Wv, const float* __restrict__ Wo)
{
    int e = blockIdx.x * 256 + threadIdx.x;
    int mat = e >> 18;
    int rem = e & 0x3FFFF;
    const float* W = (mat == 0) ? Wq : (mat == 1) ? Wk : (mat == 2) ? Wv : Wo;
    g_w[e] = __float2half_rn(__ldg(&W[rem]));
}

// ---------------------------------------------------------------------------
// GEMM core: Mtile 128 x Ntile 128 x Ktile 64, fp16, f32 accum.
// smem tiles: unpadded 128B rows with SW128 XOR swizzle (chunk16 ^= row&7):
// ldmatrix conflict-free, cp.async gmem-coalesced. Stage = A16K + B16K = 32KB;
// 3 stages = 96KB -> 2 CTAs/SM. 8 iterations, ONE __syncthreads each.
// ---------------------------------------------------------------------------
#define PIPE_BYTES 98304

__device__ __forceinline__ void gemm_pipeline(const __half* aSrc, const __half* bSrc,
                                              __half* sm, float (&acc)[2][8][4],
                                              int tid, int mbase, int nbase)
{
    const int lane = tid & 31;
    const uint32_t smBase = (uint32_t)__cvta_generic_to_shared(sm);

    // per-lane ldmatrix row bases (bytes) + XOR keys
    uint32_t aRow[2], aX[2], bRow[4], bX[4];
    const uint32_t aBit = (lane >> 4) & 1;          // A: k-chunk select
    const uint32_t bBit = (lane >> 3) & 1;          // B: k-chunk select
#pragma unroll
    for (int mi = 0; mi < 2; mi++) {
        int r = mbase + mi * 16 + (lane & 15);
        aRow[mi] = (uint32_t)(r * 128);
        aX[mi] = (uint32_t)(r & 7);
    }
#pragma unroll
    for (int p = 0; p < 4; p++) {
        int r = nbase + p * 16 + ((lane >> 4) & 1) * 8 + (lane & 7);
        bRow[p] = (uint32_t)(16384 + r * 128);
        bX[p] = (uint32_t)(r & 7);
    }

    auto issue = [&](int slot, int kt) {
        uint32_t base = (uint32_t)(slot * 32768);
#pragma unroll
        for (int j = 0; j < 4; j++) {
            int cidx = tid + j * 256;              // 0..1023
            int r = cidx >> 3, p = cidx & 7;
            uint32_t d = base + (uint32_t)(r * 128 + ((p ^ (r & 7)) * 16));
            const size_t go = (size_t)r * 512 + kt * 64 + p * 8;
            cpasync16(sm + (d >> 1), aSrc + go);
            cpasync16(sm + ((d + 16384) >> 1), bSrc + go);
        }
    };

    issue(0, 0); CP_COMMIT();
    issue(1, 1); CP_COMMIT();

#pragma unroll
    for (int it = 0; it < 8; it++) {
        if (it < 7) CP_WAIT1(); else CP_WAIT0();
        __syncthreads();
        int nx = it + 2;
        if (nx < 8) { issue(nx % 3, nx); CP_COMMIT(); }

        const uint32_t stageB = smBase + (uint32_t)((it % 3) * 32768);
#pragma unroll
        for (int ks = 0; ks < 4; ks++) {
            uint32_t a[2][4];
#pragma unroll
            for (int mi = 0; mi < 2; mi++)
                ldsm4(a[mi], stageB + aRow[mi] + (((2 * ks + aBit) ^ aX[mi]) * 16));
            uint32_t b[4][4];
#pragma unroll
            for (int p = 0; p < 4; p++)
                ldsm4(b[p], stageB + bRow[p] + (((2 * ks + bBit) ^ bX[p]) * 16));
#pragma unroll
            for (int p = 0; p < 4; p++) {
                mma_f16(acc[0][2 * p],     a[0], &b[p][0]);
                mma_f16(acc[1][2 * p],     a[1], &b[p][0]);
                mma_f16(acc[0][2 * p + 1], a[0], &b[p][2]);
                mma_f16(acc[1][2 * p + 1], a[1], &b[p][2]);
            }
        }
    }
}

// ---------------------------------------------------------------------------
// Kernel 1: QKV projection. grid (12, 1360). Epilogue identical to R11-win.
// ---------------------------------------------------------------------------
__global__ __launch_bounds__(256, 2)
void qkv_kernel(const float* __restrict__ bq, const float* __restrict__ bk,
                const float* __restrict__ bv)
{
    extern __shared__ __half sm[];

    const int tid = threadIdx.x;
    const int bn0 = blockIdx.y * 2;
    const int y   = blockIdx.x;
    const int mat = y >> 2;             // 0:q 1:k 2:v
    const int r0  = (y & 3) * 128;
    const float* bias = (mat == 0) ? bq : (mat == 1) ? bk : bv;

    const int lane = tid & 31, wid = tid >> 5;
    const int wm = wid & 3, wn = wid >> 2;
    const int g = lane >> 2, t4 = lane & 3;
    const int mbase = wm * 32, nbase = wn * 64;

    float acc[2][8][4];
#pragma unroll
    for (int mi = 0; mi < 2; mi++)
#pragma unroll
        for (int ni = 0; ni < 8; ni++)
#pragma unroll
            for (int j = 0; j < 4; j++) acc[mi][ni][j] = 0.f;

    const __half* aSrc = g_x + (size_t)(bn0 * TT) * 512;
    const __half* bSrc = g_w + (size_t)(mat * 512 + r0) * 512;

    gemm_pipeline(aSrc, bSrc, sm, acc, tid, mbase, nbase);

    // ---- epilogue: bias, fp16 pack, smem stage (stride 68 words) ----
    __syncthreads();
    uint32_t* EsW = (uint32_t*)sm;
#pragma unroll
    for (int mi = 0; mi < 2; mi++) {
        int rA = mbase + mi * 16 + g;
#pragma unroll
        for (int ni = 0; ni < 8; ni++) {
            int jj = nbase + ni * 8 + 2 * t4;
            int o = r0 + jj;
            float b0 = __ldg(&bias[o]), b1 = __ldg(&bias[o + 1]);
            EsW[rA * 68 + (jj >> 1)]       = packh2(acc[mi][ni][0] + b0, acc[mi][ni][1] + b1);
            EsW[(rA + 8) * 68 + (jj >> 1)] = packh2(acc[mi][ni][2] + b0, acc[mi][ni][3] + b1);
        }
    }
    __syncthreads();

    if (mat < 2) {
        __half* dst = (mat == 0) ? g_q : g_k;
#pragma unroll
        for (int j = 0; j < 8; j++) {
            int idx = tid + j * 256;
            int trow = idx >> 4, part = idx & 15;
            int o = r0 + part * 8;
            int h = o >> 6, dd = o & 63;
            int bn = bn0 + (trow >> 6), t = trow & 63;
            *(uint4*)(dst + (size_t)(bn * NHEAD + h) * 4096 + t * 64 + dd) =
                *(uint4*)&EsW[trow * 68 + part * 4];
        }
    } else {
        // v transposed: g_v[(bn,h)][dd][t]
        const __half* Es = sm;
#pragma unroll
        for (int j = 0; j < 8; j++) {
            int idx = tid + j * 256;
            int ddg = idx & 127;
            int tch = idx >> 7;               // 0..15
            int bnh = tch >> 3, t0 = (tch & 7) * 8;
            int o = r0 + ddg;
            int h = o >> 6, dd = o & 63;
            uint32_t w[4];
#pragma unroll
            for (int p = 0; p < 4; p++) {
                __half lo = Es[(bnh * 64 + t0 + 2 * p) * 136 + ddg];
                __half hi = Es[(bnh * 64 + t0 + 2 * p + 1) * 136 + ddg];
                w[p] = (uint32_t)__half_as_ushort(lo) | ((uint32_t)__half_as_ushort(hi) << 16);
            }
            int bn = bn0 + bnh;
            *(uint4*)(g_v + (size_t)(bn * NHEAD + h) * 4096 + dd * 64 + t0) = *(uint4*)w;
        }
    }
}

// ---------------------------------------------------------------------------
// Kernel 2: causal attention per (bn, head). Unchanged (DRAM-bound at 68%).
// ---------------------------------------------------------------------------
#define SATT 36

__global__ __launch_bounds__(128)
void attn_kernel()
{
    __shared__ __half Qs[64 * 72];   // Q -> P -> O
    __shared__ __half Ks[64 * 72];   // K -> V^T
    uint32_t* QsW = (uint32_t*)Qs;
    uint32_t* KsW = (uint32_t*)Ks;

    const int tid = threadIdx.x;
    const int lane = tid & 31, wid = tid >> 5;
    const int g = lane >> 2, t4 = lane & 3;
    const int bh = blockIdx.x;
    const size_t base = (size_t)bh * 4096;

#pragma unroll
    for (int j = 0; j < 4; j++) {
        int idx = tid + j * 128;
        int t = idx >> 3, part = idx & 7;
        *(uint4*)&QsW[t * SATT + part * 4] = *(const uint4*)(g_q + base + t * 64 + part * 8);
        *(uint4*)&KsW[t * SATT + part * 4] = *(const uint4*)(g_k + base + t * 64 + part * 8);
    }
    __syncthreads();

    const int rbase = wid * 16;
    const int rA = rbase + g, rB = rA + 8;

    float s[8][4];
#pragma unroll
    for (int ni = 0; ni < 8; ni++)
#pragma unroll
        for (int j = 0; j < 4; j++) s[ni][j] = 0.f;

#pragma unroll
    for (int ks = 0; ks < 4; ks++) {
        uint32_t a[4];
        a[0] = QsW[rA * SATT + 8 * ks + t4];
        a[1] = QsW[rB * SATT + 8 * ks + t4];
        a[2] = QsW[rA * SATT + 8 * ks + t4 + 4];
        a[3] = QsW[rB * SATT + 8 * ks + t4 + 4];
#pragma unroll
        for (int ni = 0; ni < 8; ni++) {
            uint32_t b[2];
            b[0] = KsW[(ni * 8 + g) * SATT + 8 * ks + t4];
            b[1] = KsW[(ni * 8 + g) * SATT + 8 * ks + t4 + 4];
            mma_f16(s[ni], a, b);
        }
    }

    float mx0 = -1e30f, mx1 = -1e30f;
#pragma unroll
    for (int ni = 0; ni < 8; ni++) {
        int c0 = ni * 8 + 2 * t4, c1 = c0 + 1;
        s[ni][0] = (c0 <= rA) ? s[ni][0] * 0.125f : -32767.0f;
        s[ni][1] = (c1 <= rA) ? s[ni][1] * 0.125f : -32767.0f;
        s[ni][2] = (c0 <= rB) ? s[ni][2] * 0.125f : -32767.0f;
        s[ni][3] = (c1 <= rB) ? s[ni][3] * 0.125f : -32767.0f;
        mx0 = fmaxf(mx0, fmaxf(s[ni][0], s[ni][1]));
        mx1 = fmaxf(mx1, fmaxf(s[ni][2], s[ni][3]));
    }
    mx0 = fmaxf(mx0, __shfl_xor_sync(0xffffffffu, mx0, 1));
    mx0 = fmaxf(mx0, __shfl_xor_sync(0xffffffffu, mx0, 2));
    mx1 = fmaxf(mx1, __shfl_xor_sync(0xffffffffu, mx1, 1));
    mx1 = fmaxf(mx1, __shfl_xor_sync(0xffffffffu, mx1, 2));

    float sm0 = 0.f, sm1 = 0.f;
#pragma unroll
    for (int ni = 0; ni < 8; ni++) {
        s[ni][0] = __expf(s[ni][0] - mx0); sm0 += s[ni][0];
        s[ni][1] = __expf(s[ni][1] - mx0); sm0 += s[ni][1];
        s[ni][2] = __expf(s[ni][2] - mx1); sm1 += s[ni][2];
        s[ni][3] = __expf(s[ni][3] - mx1); sm1 += s[ni][3];
    }
    sm0 += __shfl_xor_sync(0xffffffffu, sm0, 1);
    sm0 += __shfl_xor_sync(0xffffffffu, sm0, 2);
    sm1 += __shfl_xor_sync(0xffffffffu, sm1, 1);
    sm1 += __shfl_xor_sync(0xffffffffu, sm1, 2);
    float inv0 = 1.f / sm0, inv1 = 1.f / sm1;

#pragma unroll
    for (int ni = 0; ni < 8; ni++) {
        QsW[rA * SATT + ni * 4 + t4] = packh2(s[ni][0] * inv0, s[ni][1] * inv0);
        QsW[rB * SATT + ni * 4 + t4] = packh2(s[ni][2] * inv1, s[ni][3] * inv1);
    }

    __syncthreads();
#pragma unroll
    for (int j = 0; j < 4; j++) {
        int idx = tid + j * 128;
        int dd = idx >> 3, part = idx & 7;
        *(uint4*)&KsW[dd * SATT + part * 4] = *(const uint4*)(g_v + base + dd * 64 + part * 8);
    }
    __syncthreads();

    float o[8][4];
#pragma unroll
    for (int ni = 0; ni < 8; ni++)
#pragma unroll
        for (int j = 0; j < 4; j++) o[ni][j] = 0.f;

#pragma unroll
    for (int ks = 0; ks < 4; ks++) {
        uint32_t a[4];
        a[0] = QsW[rA * SATT + 8 * ks + t4];
        a[1] = QsW[rB * SATT + 8 * ks + t4];
        a[2] = QsW[rA * SATT + 8 * ks + t4 + 4];
        a[3] = QsW[rB * SATT + 8 * ks + t4 + 4];
#pragma unroll
        for (int ni = 0; ni < 8; ni++) {
            uint32_t b[2];
            b[0] = KsW[(ni * 8 + g) * SATT + 8 * ks + t4];
            b[1] = KsW[(ni * 8 + g) * SATT + 8 * ks + t4 + 4];
            mma_f16(o[ni], a, b);
        }
    }
    __syncthreads();

#pragma unroll
    for (int ni = 0; ni < 8; ni++) {
        QsW[rA * SATT + ni * 4 + t4] = packh2(o[ni][0], o[ni][1]);
        QsW[rB * SATT + ni * 4 + t4] = packh2(o[ni][2], o[ni][3]);
    }
    __syncthreads();

    const int bn = bh >> 3, h = bh & 7;
#pragma unroll
    for (int j = 0; j < 4; j++) {
        int idx = tid + j * 128;
        int t = idx >> 3, part = idx & 7;
        uint4 v = *(uint4*)&QsW[t * SATT + part * 4];
        *(uint4*)(g_o2 + ((size_t)bn * 64 + t) * 512 + h * 64 + part * 8) = v;
    }
}

// ---------------------------------------------------------------------------
// Kernel 3: output projection + bias + ReLU. grid (4, 1360).
// ---------------------------------------------------------------------------
__global__ __launch_bounds__(256, 2)
void out_kernel(const float* __restrict__ bo, float* __restrict__ out)
{
    extern __shared__ __half sm[];
    __shared__ int outOff[128];

    const int tid = threadIdx.x;
    const int m0  = blockIdx.y * 128;
    const int r0  = blockIdx.x * 128;

    if (tid < 128) {
        int token = m0 + tid;
        int bn = token >> 6;
        int b = bn / NPOS, n = bn % NPOS;
        outOff[tid] = (b * 512 * NPOS + n) * TT + (token & 63);
    }

    const int lane = tid & 31, wid = tid >> 5;
    const int wm = wid & 3, wn = wid >> 2;
    const int g = lane >> 2, t4 = lane & 3;
    const int mbase = wm * 32, nbase = wn * 64;

    float acc[2][8][4];
#pragma unroll
    for (int mi = 0; mi < 2; mi++)
#pragma unroll
        for (int ni = 0; ni < 8; ni++)
#pragma unroll
            for (int j = 0; j < 4; j++) acc[mi][ni][j] = 0.f;

    const __half* aSrc = g_o2 + (size_t)m0 * 512;
    const __half* bSrc = g_w + (size_t)(3 * 512 + r0) * 512;

    gemm_pipeline(aSrc, bSrc, sm, acc, tid, mbase, nbase);
    __syncthreads();

    // epilogue: bias + relu + scatter to [B,512,N,T] (t-contiguous 32B runs)
#pragma unroll
    for (int mi = 0; mi < 2; mi++) {
        int rloc = mbase + mi * 16 + g;
        int off0 = outOff[rloc];
        int off1 = outOff[rloc + 8];
#pragma unroll
        for (int ni = 0; ni < 8; ni++) {
            int jj = nbase + ni * 8 + 2 * t4;
            int o = r0 + jj;
            float b0 = __ldg(&bo[o]), b1 = __ldg(&bo[o + 1]);
            out[off0 + o * NTSTR]       = fmaxf(acc[mi][ni][0] + b0, 0.f);
            out[off0 + (o + 1) * NTSTR] = fmaxf(acc[mi][ni][1] + b1, 0.f);
            out[off1 + o * NTSTR]       = fmaxf(acc[mi][ni][2] + b0, 0.f);
            out[off1 + (o + 1) * NTSTR] = fmaxf(acc[mi][ni][3] + b1, 0.f);
        }
    }
}

// ---------------------------------------------------------------------------
extern "C" void kernel_launch(void* const* d_in, const int* in_sizes, int n_in,
                              void* d_out, int out_size)
{
    const float* x   = (const float*)d_in[0];
    const float* tem = (const float*)d_in[1];
    const float* Wq  = (const float*)d_in[2];
    const float* bq  = (const float*)d_in[3];
    const float* Wk  = (const float*)d_in[4];
    const float* bk  = (const float*)d_in[5];
    const float* Wv  = (const float*)d_in[6];
    const float* bv  = (const float*)d_in[7];
    const float* Wo  = (const float*)d_in[8];
    const float* bo  = (const float*)d_in[9];
    float* out = (float*)d_out;

    cudaFuncSetAttribute(qkv_kernel, cudaFuncAttributeMaxDynamicSharedMemorySize, PIPE_BYTES);
    cudaFuncSetAttribute(out_kernel, cudaFuncAttributeMaxDynamicSharedMemorySize, PIPE_BYTES);

    cvt_x_kernel<<<BN, 256>>>(x, tem);
    cvt_w_kernel<<<4096, 256>>>(Wq, Wk, Wv, Wo);

    dim3 g1(12, BN / 2);
    qkv_kernel<<<g1, 256, PIPE_BYTES>>>(bq, bk, bv);

    attn_kernel<<<BN * NHEAD, 128>>>();

    dim3 g3(4, BN / 2);
    out_kernel<<<g3, 256, PIPE_BYTES>>>(bo, out);
}

// round 17
// speedup vs baseline: 1.5305x; 1.0107x over previous
#include <cuda_runtime.h>
#include <cuda_fp16.h>
#include <cstdint>

#define BATCH   16
#define CHX     256
#define NPOS    170
#define TT      64
#define NHEAD   8
#define HDIM    64
#define BN      (BATCH*NPOS)      // 2720
#define TOKENS  (BN*TT)           // 174080
#define NTSTR   (NPOS*TT)         // 10880
#define QE      (TOKENS*512)      // 89,128,960

// Device scratch (fp16). g_x/g_o2: [token][c 512]. g_q/g_k: per-(bn,h) [t][dd].
// g_v: per-(bn,h) [dd][t] (pre-transposed).
__device__ __half g_x[QE];
__device__ __half g_w[4*512*512];   // [mat][n][k] row-major
__device__ __half g_q[QE];
__device__ __half g_k[QE];
__device__ __half g_v[QE];
__device__ __half g_o2[QE];

// ---------------------------------------------------------------------------
__device__ __forceinline__ void mma_f16(float* d, const uint32_t* a, const uint32_t* b) {
    asm volatile(
        "mma.sync.aligned.m16n8k16.row.col.f32.f16.f16.f32 "
        "{%0,%1,%2,%3},{%4,%5,%6,%7},{%8,%9},{%0,%1,%2,%3};\n"
        : "+f"(d[0]), "+f"(d[1]), "+f"(d[2]), "+f"(d[3])
        : "r"(a[0]), "r"(a[1]), "r"(a[2]), "r"(a[3]),
          "r"(b[0]), "r"(b[1]));
}

__device__ __forceinline__ void ldsm4(uint32_t* r, uint32_t addr) {
    asm volatile("ldmatrix.sync.aligned.m8n8.x4.shared.b16 {%0,%1,%2,%3}, [%4];"
                 : "=r"(r[0]), "=r"(r[1]), "=r"(r[2]), "=r"(r[3]) : "r"(addr));
}

__device__ __forceinline__ uint32_t packh2(float a, float b) {
    __half2 h = __floats2half2_rn(a, b);
    return *(uint32_t*)&h;
}

__device__ __forceinline__ void cpasync16(__half* smem_dst, const __half* gsrc) {
    uint32_t s = (uint32_t)__cvta_generic_to_shared(smem_dst);
    asm volatile("cp.async.cg.shared.global [%0], [%1], 16;\n"
                 :: "r"(s), "l"(gsrc) : "memory");
}
#define CP_COMMIT() asm volatile("cp.async.commit_group;\n" ::: "memory")
#define CP_WAIT1()  asm volatile("cp.async.wait_group 1;\n" ::: "memory")
#define CP_WAIT0()  asm volatile("cp.async.wait_group 0;\n" ::: "memory")

// ---------------------------------------------------------------------------
// Prepass 1: x||tem -> g_x fp16 [token][c], via smem transpose.
// Vectorized stores: each thread packs 8 channels -> one uint4 STG.
// ---------------------------------------------------------------------------
__global__ void cvt_x_kernel(const float* __restrict__ x, const float* __restrict__ tem)
{
    __shared__ float smt[64 * 67];
    const int blk = blockIdx.x;
    const int b = blk / NPOS, n = blk % NPOS;
    const int tid = threadIdx.x;

    for (int chunk = 0; chunk < 8; chunk++) {
        const int c0 = chunk * 64;
        const float* src = (c0 < CHX)
            ? x   + (size_t)(b * CHX + c0) * NTSTR
            : tem + (size_t)(b * CHX + c0 - CHX) * NTSTR;
#pragma unroll
        for (int i = 0; i < 16; i++) {
            int idx = tid + i * 256;
            int cl = idx >> 6, t = idx & 63;
            smt[cl * 67 + t] = __ldg(&src[(size_t)cl * NTSTR + n * TT + t]);
        }
        __syncthreads();
        // 64 t x 8 groups of 8 channels = 512 uint4 stores; 2 per thread
#pragma unroll
        for (int i = 0; i < 2; i++) {
            int idx = tid + i * 256;
            int t = idx >> 3, grp = idx & 7;
            uint32_t w[4];
#pragma unroll
            for (int p = 0; p < 4; p++)
                w[p] = packh2(smt[(grp * 8 + 2 * p) * 67 + t],
                              smt[(grp * 8 + 2 * p + 1) * 67 + t]);
            __stcs((uint4*)(g_x + ((size_t)(b * NPOS + n) * TT + t) * 512 + c0 + grp * 8),
                   *(uint4*)w);
        }
        __syncthreads();
    }
}

// ---------------------------------------------------------------------------
// Prepass 2: weights -> g_w fp16 [mat][n][k].
// ---------------------------------------------------------------------------
__global__ void cvt_w_kernel(const float* __restrict__ Wq, const float* __restrict__ Wk,
                             const float* __restrict__ Wv, const float* __restrict__ Wo)
{
    int e = blockIdx.x * 256 + threadIdx.x;
    int mat = e >> 18;
    int rem = e & 0x3FFFF;
    const float* W = (mat == 0) ? Wq : (mat == 1) ? Wk : (mat == 2) ? Wv : Wo;
    g_w[e] = __float2half_rn(__ldg(&W[rem]));
}

// ---------------------------------------------------------------------------
// GEMM core: Mtile 128 x Ntile 128 x Ktile 64, fp16, f32 accum.
// Unpadded 128B rows + SW128 XOR swizzle; 3 stages x 32KB = 96KB, 2 CTAs/SM;
// 8 iterations, ONE __syncthreads each.  (R15-win; FROZEN)
// ---------------------------------------------------------------------------
#define PIPE_BYTES 98304

__device__ __forceinline__ void gemm_pipeline(const __half* aSrc, const __half* bSrc,
                                              __half* sm, float (&acc)[2][8][4],
                                              int tid, int mbase, int nbase)
{
    const int lane = tid & 31;
    const uint32_t smBase = (uint32_t)__cvta_generic_to_shared(sm);

    uint32_t aRow[2], aX[2], bRow[4], bX[4];
    const uint32_t aBit = (lane >> 4) & 1;
    const uint32_t bBit = (lane >> 3) & 1;
#pragma unroll
    for (int mi = 0; mi < 2; mi++) {
        int r = mbase + mi * 16 + (lane & 15);
        aRow[mi] = (uint32_t)(r * 128);
        aX[mi] = (uint32_t)(r & 7);
    }
#pragma unroll
    for (int p = 0; p < 4; p++) {
        int r = nbase + p * 16 + ((lane >> 4) & 1) * 8 + (lane & 7);
        bRow[p] = (uint32_t)(16384 + r * 128);
        bX[p] = (uint32_t)(r & 7);
    }

    auto issue = [&](int slot, int kt) {
        uint32_t base = (uint32_t)(slot * 32768);
#pragma unroll
        for (int j = 0; j < 4; j++) {
            int cidx = tid + j * 256;
            int r = cidx >> 3, p = cidx & 7;
            uint32_t d = base + (uint32_t)(r * 128 + ((p ^ (r & 7)) * 16));
            const size_t go = (size_t)r * 512 + kt * 64 + p * 8;
            cpasync16(sm + (d >> 1), aSrc + go);
            cpasync16(sm + ((d + 16384) >> 1), bSrc + go);
        }
    };

    issue(0, 0); CP_COMMIT();
    issue(1, 1); CP_COMMIT();

#pragma unroll
    for (int it = 0; it < 8; it++) {
        if (it < 7) CP_WAIT1(); else CP_WAIT0();
        __syncthreads();
        int nx = it + 2;
        if (nx < 8) { issue(nx % 3, nx); CP_COMMIT(); }

        const uint32_t stageB = smBase + (uint32_t)((it % 3) * 32768);
#pragma unroll
        for (int ks = 0; ks < 4; ks++) {
            uint32_t a[2][4];
#pragma unroll
            for (int mi = 0; mi < 2; mi++)
                ldsm4(a[mi], stageB + aRow[mi] + (((2 * ks + aBit) ^ aX[mi]) * 16));
            uint32_t b[4][4];
#pragma unroll
            for (int p = 0; p < 4; p++)
                ldsm4(b[p], stageB + bRow[p] + (((2 * ks + bBit) ^ bX[p]) * 16));
#pragma unroll
            for (int p = 0; p < 4; p++) {
                mma_f16(acc[0][2 * p],     a[0], &b[p][0]);
                mma_f16(acc[1][2 * p],     a[1], &b[p][0]);
                mma_f16(acc[0][2 * p + 1], a[0], &b[p][2]);
                mma_f16(acc[1][2 * p + 1], a[1], &b[p][2]);
            }
        }
    }
}

// ---------------------------------------------------------------------------
// Kernel 1: QKV projection. grid (12, 1360). Streaming stores for g_q/g_k/g_v
// (re-read far later; keep them out of L2).
// ---------------------------------------------------------------------------
__global__ __launch_bounds__(256, 2)
void qkv_kernel(const float* __restrict__ bq, const float* __restrict__ bk,
                const float* __restrict__ bv)
{
    extern __shared__ __half sm[];

    const int tid = threadIdx.x;
    const int bn0 = blockIdx.y * 2;
    const int y   = blockIdx.x;
    const int mat = y >> 2;             // 0:q 1:k 2:v
    const int r0  = (y & 3) * 128;
    const float* bias = (mat == 0) ? bq : (mat == 1) ? bk : bv;

    const int lane = tid & 31, wid = tid >> 5;
    const int wm = wid & 3, wn = wid >> 2;
    const int g = lane >> 2, t4 = lane & 3;
    const int mbase = wm * 32, nbase = wn * 64;

    float acc[2][8][4];
#pragma unroll
    for (int mi = 0; mi < 2; mi++)
#pragma unroll
        for (int ni = 0; ni < 8; ni++)
#pragma unroll
            for (int j = 0; j < 4; j++) acc[mi][ni][j] = 0.f;

    const __half* aSrc = g_x + (size_t)(bn0 * TT) * 512;
    const __half* bSrc = g_w + (size_t)(mat * 512 + r0) * 512;

    gemm_pipeline(aSrc, bSrc, sm, acc, tid, mbase, nbase);

    // ---- epilogue: bias, fp16 pack, smem stage (stride 68 words) ----
    __syncthreads();
    uint32_t* EsW = (uint32_t*)sm;
#pragma unroll
    for (int mi = 0; mi < 2; mi++) {
        int rA = mbase + mi * 16 + g;
#pragma unroll
        for (int ni = 0; ni < 8; ni++) {
            int jj = nbase + ni * 8 + 2 * t4;
            int o = r0 + jj;
            float b0 = __ldg(&bias[o]), b1 = __ldg(&bias[o + 1]);
            EsW[rA * 68 + (jj >> 1)]       = packh2(acc[mi][ni][0] + b0, acc[mi][ni][1] + b1);
            EsW[(rA + 8) * 68 + (jj >> 1)] = packh2(acc[mi][ni][2] + b0, acc[mi][ni][3] + b1);
        }
    }
    __syncthreads();

    if (mat < 2) {
        __half* dst = (mat == 0) ? g_q : g_k;
#pragma unroll
        for (int j = 0; j < 8; j++) {
            int idx = tid + j * 256;
            int trow = idx >> 4, part = idx & 15;
            int o = r0 + part * 8;
            int h = o >> 6, dd = o & 63;
            int bn = bn0 + (trow >> 6), t = trow & 63;
            __stcs((uint4*)(dst + (size_t)(bn * NHEAD + h) * 4096 + t * 64 + dd),
                   *(uint4*)&EsW[trow * 68 + part * 4]);
        }
    } else {
        // v transposed: g_v[(bn,h)][dd][t]
        const __half* Es = sm;
#pragma unroll
        for (int j = 0; j < 8; j++) {
            int idx = tid + j * 256;
            int ddg = idx & 127;
            int tch = idx >> 7;               // 0..15
            int bnh = tch >> 3, t0 = (tch & 7) * 8;
            int o = r0 + ddg;
            int h = o >> 6, dd = o & 63;
            uint32_t w[4];
#pragma unroll
            for (int p = 0; p < 4; p++) {
                __half lo = Es[(bnh * 64 + t0 + 2 * p) * 136 + ddg];
                __half hi = Es[(bnh * 64 + t0 + 2 * p + 1) * 136 + ddg];
                w[p] = (uint32_t)__half_as_ushort(lo) | ((uint32_t)__half_as_ushort(hi) << 16);
            }
            int bn = bn0 + bnh;
            __stcs((uint4*)(g_v + (size_t)(bn * NHEAD + h) * 4096 + dd * 64 + t0),
                   *(uint4*)w);
        }
    }
}

// ---------------------------------------------------------------------------
// Kernel 2: causal attention per (bn, head). Unchanged (DRAM-bound at 68%).
// ---------------------------------------------------------------------------
#define SATT 36

__global__ __launch_bounds__(128)
void attn_kernel()
{
    __shared__ __half Qs[64 * 72];   // Q -> P -> O
    __shared__ __half Ks[64 * 72];   // K -> V^T
    uint32_t* QsW = (uint32_t*)Qs;
    uint32_t* KsW = (uint32_t*)Ks;

    const int tid = threadIdx.x;
    const int lane = tid & 31, wid = tid >> 5;
    const int g = lane >> 2, t4 = lane & 3;
    const int bh = blockIdx.x;
    const size_t base = (size_t)bh * 4096;

#pragma unroll
    for (int j = 0; j < 4; j++) {
        int idx = tid + j * 128;
        int t = idx >> 3, part = idx & 7;
        *(uint4*)&QsW[t * SATT + part * 4] = __ldcs((const uint4*)(g_q + base + t * 64 + part * 8));
        *(uint4*)&KsW[t * SATT + part * 4] = __ldcs((const uint4*)(g_k + base + t * 64 + part * 8));
    }
    __syncthreads();

    const int rbase = wid * 16;
    const int rA = rbase + g, rB = rA + 8;

    float s[8][4];
#pragma unroll
    for (int ni = 0; ni < 8; ni++)
#pragma unroll
        for (int j = 0; j < 4; j++) s[ni][j] = 0.f;

#pragma unroll
    for (int ks = 0; ks < 4; ks++) {
        uint32_t a[4];
        a[0] = QsW[rA * SATT + 8 * ks + t4];
        a[1] = QsW[rB * SATT + 8 * ks + t4];
        a[2] = QsW[rA * SATT + 8 * ks + t4 + 4];
        a[3] = QsW[rB * SATT + 8 * ks + t4 + 4];
#pragma unroll
        for (int ni = 0; ni < 8; ni++) {
            uint32_t b[2];
            b[0] = KsW[(ni * 8 + g) * SATT + 8 * ks + t4];
            b[1] = KsW[(ni * 8 + g) * SATT + 8 * ks + t4 + 4];
            mma_f16(s[ni], a, b);
        }
    }

    float mx0 = -1e30f, mx1 = -1e30f;
#pragma unroll
    for (int ni = 0; ni < 8; ni++) {
        int c0 = ni * 8 + 2 * t4, c1 = c0 + 1;
        s[ni][0] = (c0 <= rA) ? s[ni][0] * 0.125f : -32767.0f;
        s[ni][1] = (c1 <= rA) ? s[ni][1] * 0.125f : -32767.0f;
        s[ni][2] = (c0 <= rB) ? s[ni][2] * 0.125f : -32767.0f;
        s[ni][3] = (c1 <= rB) ? s[ni][3] * 0.125f : -32767.0f;
        mx0 = fmaxf(mx0, fmaxf(s[ni][0], s[ni][1]));
        mx1 = fmaxf(mx1, fmaxf(s[ni][2], s[ni][3]));
    }
    mx0 = fmaxf(mx0, __shfl_xor_sync(0xffffffffu, mx0, 1));
    mx0 = fmaxf(mx0, __shfl_xor_sync(0xffffffffu, mx0, 2));
    mx1 = fmaxf(mx1, __shfl_xor_sync(0xffffffffu, mx1, 1));
    mx1 = fmaxf(mx1, __shfl_xor_sync(0xffffffffu, mx1, 2));

    float sm0 = 0.f, sm1 = 0.f;
#pragma unroll
    for (int ni = 0; ni < 8; ni++) {
        s[ni][0] = __expf(s[ni][0] - mx0); sm0 += s[ni][0];
        s[ni][1] = __expf(s[ni][1] - mx0); sm0 += s[ni][1];
        s[ni][2] = __expf(s[ni][2] - mx1); sm1 += s[ni][2];
        s[ni][3] = __expf(s[ni][3] - mx1); sm1 += s[ni][3];
    }
    sm0 += __shfl_xor_sync(0xffffffffu, sm0, 1);
    sm0 += __shfl_xor_sync(0xffffffffu, sm0, 2);
    sm1 += __shfl_xor_sync(0xffffffffu, sm1, 1);
    sm1 += __shfl_xor_sync(0xffffffffu, sm1, 2);
    float inv0 = 1.f / sm0, inv1 = 1.f / sm1;

#pragma unroll
    for (int ni = 0; ni < 8; ni++) {
        QsW[rA * SATT + ni * 4 + t4] = packh2(s[ni][0] * inv0, s[ni][1] * inv0);
        QsW[rB * SATT + ni * 4 + t4] = packh2(s[ni][2] * inv1, s[ni][3] * inv1);
    }

    __syncthreads();
#pragma unroll
    for (int j = 0; j < 4; j++) {
        int idx = tid + j * 128;
        int dd = idx >> 3, part = idx & 7;
        *(uint4*)&KsW[dd * SATT + part * 4] = __ldcs((const uint4*)(g_v + base + dd * 64 + part * 8));
    }
    __syncthreads();

    float o[8][4];
#pragma unroll
    for (int ni = 0; ni < 8; ni++)
#pragma unroll
        for (int j = 0; j < 4; j++) o[ni][j] = 0.f;

#pragma unroll
    for (int ks = 0; ks < 4; ks++) {
        uint32_t a[4];
        a[0] = QsW[rA * SATT + 8 * ks + t4];
        a[1] = QsW[rB * SATT + 8 * ks + t4];
        a[2] = QsW[rA * SATT + 8 * ks + t4 + 4];
        a[3] = QsW[rB * SATT + 8 * ks + t4 + 4];
#pragma unroll
        for (int ni = 0; ni < 8; ni++) {
            uint32_t b[2];
            b[0] = KsW[(ni * 8 + g) * SATT + 8 * ks + t4];
            b[1] = KsW[(ni * 8 + g) * SATT + 8 * ks + t4 + 4];
            mma_f16(o[ni], a, b);
        }
    }
    __syncthreads();

#pragma unroll
    for (int ni = 0; ni < 8; ni++) {
        QsW[rA * SATT + ni * 4 + t4] = packh2(o[ni][0], o[ni][1]);
        QsW[rB * SATT + ni * 4 + t4] = packh2(o[ni][2], o[ni][3]);
    }
    __syncthreads();

    const int bn = bh >> 3, h = bh & 7;
#pragma unroll
    for (int j = 0; j < 4; j++) {
        int idx = tid + j * 128;
        int t = idx >> 3, part = idx & 7;
        uint4 v = *(uint4*)&QsW[t * SATT + part * 4];
        *(uint4*)(g_o2 + ((size_t)bn * 64 + t) * 512 + h * 64 + part * 8) = v;
    }
}

// ---------------------------------------------------------------------------
// Kernel 3: output projection + bias + ReLU. grid (4, 1360). Streaming output
// stores (never re-read).
// ---------------------------------------------------------------------------
__global__ __launch_bounds__(256, 2)
void out_kernel(const float* __restrict__ bo, float* __restrict__ out)
{
    extern __shared__ __half sm[];
    __shared__ int outOff[128];

    const int tid = threadIdx.x;
    const int m0  = blockIdx.y * 128;
    const int r0  = blockIdx.x * 128;

    if (tid < 128) {
        int token = m0 + tid;
        int bn = token >> 6;
        int b = bn / NPOS, n = bn % NPOS;
        outOff[tid] = (b * 512 * NPOS + n) * TT + (token & 63);
    }

    const int lane = tid & 31, wid = tid >> 5;
    const int wm = wid & 3, wn = wid >> 2;
    const int g = lane >> 2, t4 = lane & 3;
    const int mbase = wm * 32, nbase = wn * 64;

    float acc[2][8][4];
#pragma unroll
    for (int mi = 0; mi < 2; mi++)
#pragma unroll
        for (int ni = 0; ni < 8; ni++)
#pragma unroll
            for (int j = 0; j < 4; j++) acc[mi][ni][j] = 0.f;

    const __half* aSrc = g_o2 + (size_t)m0 * 512;
    const __half* bSrc = g_w + (size_t)(3 * 512 + r0) * 512;

    gemm_pipeline(aSrc, bSrc, sm, acc, tid, mbase, nbase);
    __syncthreads();

    // epilogue: bias + relu + streaming scatter to [B,512,N,T]
#pragma unroll
    for (int mi = 0; mi < 2; mi++) {
        int rloc = mbase + mi * 16 + g;
        int off0 = outOff[rloc];
        int off1 = outOff[rloc + 8];
#pragma unroll
        for (int ni = 0; ni < 8; ni++) {
            int jj = nbase + ni * 8 + 2 * t4;
            int o = r0 + jj;
            float b0 = __ldg(&bo[o]), b1 = __ldg(&bo[o + 1]);
            __stcs(&out[off0 + o * NTSTR],       fmaxf(acc[mi][ni][0] + b0, 0.f));
            __stcs(&out[off0 + (o + 1) * NTSTR], fmaxf(acc[mi][ni][1] + b1, 0.f));
            __stcs(&out[off1 + o * NTSTR],       fmaxf(acc[mi][ni][2] + b0, 0.f));
            __stcs(&out[off1 + (o + 1) * NTSTR], fmaxf(acc[mi][ni][3] + b1, 0.f));
        }
    }
}

// ---------------------------------------------------------------------------
extern "C" void kernel_launch(void* const* d_in, const int* in_sizes, int n_in,
                              void* d_out, int out_size)
{
    const float* x   = (const float*)d_in[0];
    const float* tem = (const float*)d_in[1];
    const float* Wq  = (const float*)d_in[2];
    const float* bq  = (const float*)d_in[3];
    const float* Wk  = (const float*)d_in[4];
    const float* bk  = (const float*)d_in[5];
    const float* Wv  = (const float*)d_in[6];
    const float* bv  = (const float*)d_in[7];
    const float* Wo  = (const float*)d_in[8];
    const float* bo  = (const float*)d_in[9];
    float* out = (float*)d_out;

    cudaFuncSetAttribute(qkv_kernel, cudaFuncAttributeMaxDynamicSharedMemorySize, PIPE_BYTES);
    cudaFuncSetAttribute(out_kernel, cudaFuncAttributeMaxDynamicSharedMemorySize, PIPE_BYTES);

    cvt_x_kernel<<<BN, 256>>>(x, tem);
    cvt_w_kernel<<<4096, 256>>>(Wq, Wk, Wv, Wo);

    dim3 g1(12, BN / 2);
    qkv_kernel<<<g1, 256, PIPE_BYTES>>>(bq, bk, bv);

    attn_kernel<<<BN * NHEAD, 128>>>();

    dim3 g3(4, BN / 2);
    out_kernel<<<g3, 256, PIPE_BYTES>>>(bo, out);
}